// round 2
// baseline (speedup 1.0000x reference)
#include <cuda_runtime.h>

#define BATCH 8
#define C 64
#define N 4096
#define KNN 20
#define NOUT 64
#define SLOPE 0.01f
#define NEG_INF -1e30f

typedef unsigned long long u64;

// Scratch (device globals: no allocation allowed)
__device__ float g_xx[BATCH * N];            // ||x_n||^2
__device__ int   g_idx[BATCH * N * KNN];     // top-K neighbor indices
__device__ float g_g[BATCH * N * NOUT];      // [b][m][o] : W1 . x_m
__device__ float g_u[BATCH * N * NOUT];      // [b][n][o] : (W2-W1) . x_n

// packed fp32x2 FMA — sm_103a FFMA2, only reachable via explicit PTX
#define FMA_F32X2(d, a, b) \
    asm("fma.rn.f32x2 %0, %1, %2, %0;" : "+l"(d) : "l"(a), "l"(b))

// ---------------------------------------------------------------------------
// Kernel A: xx[b][n] = sum_c x[b][c][n]^2
// ---------------------------------------------------------------------------
__global__ void xx_kernel(const float* __restrict__ x) {
    int b = blockIdx.y;
    int n = blockIdx.x * 256 + threadIdx.x;
    const float* xb = x + (size_t)b * C * N;
    float s = 0.f;
#pragma unroll
    for (int c = 0; c < C; c++) {
        float v = xb[c * N + n];
        s = fmaf(v, v, s);
    }
    g_xx[b * N + n] = s;
}

// ---------------------------------------------------------------------------
// Kernel B: fused Gram-tile GEMM (FFMA2 packed fp32) + top-K selection.
// CTA: 128 n-rows of one batch, loops over 32 m-tiles of 128.
// A-operand stored DUPLICATED in smem so LDS.128 yields broadcast f32x2 pairs.
// ---------------------------------------------------------------------------
#define BN 128
#define BM 128
#define DPAD 129
// smem floats: xnd 64*256 (duplicated), xm 64*128, dist 128*129, xxm 128
#define KNN_SMEM_FLOATS (64 * 256 + 64 * 128 + 128 * DPAD + 128)
#define KNN_SMEM_BYTES (KNN_SMEM_FLOATS * 4)

extern __shared__ float smem[];

__global__ __launch_bounds__(256, 1) void knn_kernel(const float* __restrict__ x) {
    int b = blockIdx.y;
    int n0 = blockIdx.x * BN;
    float* xnd   = smem;                        // [64][256] duplicated pairs
    float* xm_s  = xnd + 64 * 256;              // [64][128]
    float* dist_s = xm_s + 64 * 128;            // [m][n], pad 129
    float* xxm_s = dist_s + 128 * DPAD;         // [128]

    const float* xb = x + (size_t)b * C * N;
    int tid = threadIdx.x;
    int tx = tid & 15;        // m micro-tile
    int ty = tid >> 4;        // n micro-tile

    // load n-tile duplicated: xnd[c][2j] = xnd[c][2j+1] = x[c][n0+j]
    {
        int j = tid & 127, c0 = tid >> 7;
        for (int c = c0; c < 64; c += 2) {
            float v = xb[c * N + n0 + j];
            *(float2*)&xnd[c * 256 + 2 * j] = make_float2(v, v);
        }
    }

    float tv[KNN];
    int   ti[KNN];
#pragma unroll
    for (int k = 0; k < KNN; k++) { tv[k] = NEG_INF; ti[k] = 0; }

    for (int m0 = 0; m0 < N; m0 += BM) {
        __syncthreads();   // previous scan done; also covers xnd on first iter
        {
            int j = tid & 127, c0 = tid >> 7;
            for (int c = c0; c < 64; c += 2)
                xm_s[c * 128 + j] = xb[c * N + m0 + j];
            if (tid < 128) xxm_s[tid] = g_xx[b * N + m0 + tid];
        }
        __syncthreads();

        // --- 128x128 tile GEMM, 8x8 per thread, packed f32x2 along j ---
        u64 acc[8][4];
#pragma unroll
        for (int i = 0; i < 8; i++)
#pragma unroll
            for (int jp = 0; jp < 4; jp++) acc[i][jp] = 0ull;  // (0.f,0.f)

#pragma unroll 4
        for (int c = 0; c < 64; c++) {
            const float4* ap = (const float4*)&xnd[c * 256 + ty * 16];
            float4 A0 = ap[0], A1 = ap[1], A2 = ap[2], A3 = ap[3];
            float4 B0 = *(const float4*)&xm_s[c * 128 + tx * 8];
            float4 B1 = *(const float4*)&xm_s[c * 128 + tx * 8 + 4];
            u64 ad[8];
            ad[0] = ((const u64*)&A0)[0]; ad[1] = ((const u64*)&A0)[1];
            ad[2] = ((const u64*)&A1)[0]; ad[3] = ((const u64*)&A1)[1];
            ad[4] = ((const u64*)&A2)[0]; ad[5] = ((const u64*)&A2)[1];
            ad[6] = ((const u64*)&A3)[0]; ad[7] = ((const u64*)&A3)[1];
            u64 bp[4];
            bp[0] = ((const u64*)&B0)[0]; bp[1] = ((const u64*)&B0)[1];
            bp[2] = ((const u64*)&B1)[0]; bp[3] = ((const u64*)&B1)[1];
#pragma unroll
            for (int i = 0; i < 8; i++)
#pragma unroll
                for (int jp = 0; jp < 4; jp++)
                    FMA_F32X2(acc[i][jp], ad[i], bp[jp]);
        }

        // write score tile transposed: dist_s[m_local][n_local]
#pragma unroll
        for (int jp = 0; jp < 4; jp++) {
#pragma unroll
            for (int u = 0; u < 2; u++) {
                int j = jp * 2 + u;
                float xxv = xxm_s[tx * 8 + j];
#pragma unroll
                for (int i = 0; i < 8; i++) {
                    float a = ((const float*)&acc[i][jp])[u];
                    dist_s[(tx * 8 + j) * DPAD + ty * 8 + i] = fmaf(2.f, a, -xxv);
                }
            }
        }
        __syncthreads();

        // --- top-K scan: thread t owns row n_local = t ---
        if (tid < 128) {
            for (int m = 0; m < 128; m++) {
                float s = dist_s[m * DPAD + tid];
                if (s > tv[KNN - 1]) {             // strict: keeps earlier index on ties
                    float v = s; int vi = m0 + m;
#pragma unroll
                    for (int k = 0; k < KNN; k++) {
                        if (v > tv[k]) {
                            float t1 = tv[k]; tv[k] = v; v = t1;
                            int   t2 = ti[k]; ti[k] = vi; vi = t2;
                        }
                    }
                }
            }
        }
    }

    if (tid < 128) {
        int n = n0 + tid;
#pragma unroll
        for (int k = 0; k < KNN; k++)
            g_idx[(b * N + n) * KNN + k] = ti[k];
    }
}

// ---------------------------------------------------------------------------
// Kernel C: g[b][m][o] = W1[o,:].x[:,m],  u[b][m][o] = (W2-W1)[o,:].x[:,m]
// ---------------------------------------------------------------------------
__global__ void proj_kernel(const float* __restrict__ x, const float* __restrict__ W) {
    __shared__ float Ws[64 * 128];
    int b = blockIdx.y;
    int m = blockIdx.x * 128 + threadIdx.x;
    for (int i = threadIdx.x; i < 64 * 128; i += 128) Ws[i] = W[i];
    __syncthreads();

    const float* xb = x + (size_t)b * C * N;
    float xr[64];
#pragma unroll
    for (int c = 0; c < 64; c++) xr[c] = xb[c * N + m];

    float* gp = g_g + ((size_t)b * N + m) * NOUT;
    float* up = g_u + ((size_t)b * N + m) * NOUT;

    for (int o = 0; o < 64; o += 4) {
        float ag[4] = {0.f, 0.f, 0.f, 0.f};
        float at[4] = {0.f, 0.f, 0.f, 0.f};
#pragma unroll
        for (int q = 0; q < 4; q++) {
#pragma unroll
            for (int c4 = 0; c4 < 16; c4++) {
                float4 w1 = *(const float4*)&Ws[(o + q) * 128 + c4 * 4];
                float4 w2 = *(const float4*)&Ws[(o + q) * 128 + 64 + c4 * 4];
                ag[q] = fmaf(w1.x, xr[c4 * 4 + 0], ag[q]);
                ag[q] = fmaf(w1.y, xr[c4 * 4 + 1], ag[q]);
                ag[q] = fmaf(w1.z, xr[c4 * 4 + 2], ag[q]);
                ag[q] = fmaf(w1.w, xr[c4 * 4 + 3], ag[q]);
                at[q] = fmaf(w2.x, xr[c4 * 4 + 0], at[q]);
                at[q] = fmaf(w2.y, xr[c4 * 4 + 1], at[q]);
                at[q] = fmaf(w2.z, xr[c4 * 4 + 2], at[q]);
                at[q] = fmaf(w2.w, xr[c4 * 4 + 3], at[q]);
            }
        }
        float4 gv = make_float4(ag[0], ag[1], ag[2], ag[3]);
        float4 uv = make_float4(at[0] - ag[0], at[1] - ag[1], at[2] - ag[2], at[3] - ag[3]);
        *(float4*)&gp[o] = gv;
        *(float4*)&up[o] = uv;
    }
}

// ---------------------------------------------------------------------------
// Kernel D: out[b][o][n] = lrelu( max_k ( g[b][idx[n][k]][o] + u[b][n][o] ) )
// ---------------------------------------------------------------------------
__global__ void out_kernel(float* __restrict__ out) {
    __shared__ float os[64 * 33];
    int b = blockIdx.y;
    int w = threadIdx.x >> 5, lane = threadIdx.x & 31;
    int n = blockIdx.x * 32 + w;

    const float* up = g_u + ((size_t)b * N + n) * NOUT;
    float u0 = up[lane], u1 = up[lane + 32];
    const int* ip = g_idx + ((size_t)b * N + n) * KNN;

    float best0 = NEG_INF, best1 = NEG_INF;
#pragma unroll
    for (int k = 0; k < KNN; k++) {
        int m = ip[k];
        const float* gp = g_g + ((size_t)b * N + m) * NOUT;
        best0 = fmaxf(best0, gp[lane] + u0);
        best1 = fmaxf(best1, gp[lane + 32] + u1);
    }
    best0 = best0 >= 0.f ? best0 : SLOPE * best0;
    best1 = best1 >= 0.f ? best1 : SLOPE * best1;

    os[lane * 33 + w] = best0;
    os[(lane + 32) * 33 + w] = best1;
    __syncthreads();

    for (int i = threadIdx.x; i < 64 * 32; i += 1024) {
        int o = i >> 5, j = i & 31;
        out[((size_t)b * 64 + o) * N + blockIdx.x * 32 + j] = os[o * 33 + j];
    }
}

// ---------------------------------------------------------------------------
extern "C" void kernel_launch(void* const* d_in, const int* in_sizes, int n_in,
                              void* d_out, int out_size) {
    const float* x = (const float*)d_in[0];   // (8, 64, 4096)
    const float* W = (const float*)d_in[1];   // (64, 128)
    float* out = (float*)d_out;               // (8, 64, 4096)

    cudaFuncSetAttribute(knn_kernel, cudaFuncAttributeMaxDynamicSharedMemorySize,
                         KNN_SMEM_BYTES);

    xx_kernel<<<dim3(N / 256, BATCH), 256>>>(x);
    knn_kernel<<<dim3(N / BN, BATCH), 256, KNN_SMEM_BYTES>>>(x);
    proj_kernel<<<dim3(N / 128, BATCH), 128>>>(x, W);
    out_kernel<<<dim3(N / 32, BATCH), 1024>>>(out);
}

// round 4
// speedup vs baseline: 1.0785x; 1.0785x over previous
#include <cuda_runtime.h>
#include <cuda_bf16.h>
#include <cstdint>

#define BATCH 8
#define C 64
#define N 4096
#define KNN 20
#define K2 24            // approx candidates kept before exact rescore
#define NOUT 64
#define SLOPE 0.01f
#define NEG_INF -1e30f

typedef unsigned int u32;

// ---------------- scratch (device globals; no allocation allowed) ----------
__device__ float          g_xx[BATCH * N];            // exact ||x_n||^2
__device__ __nv_bfloat16  g_xhi[BATCH * N * C];       // [b][n][c] bf16 hi
__device__ __nv_bfloat16  g_xlo[BATCH * N * C];       // [b][n][c] bf16 lo
__device__ float          g_xt[BATCH * N * C];        // [b][n][c] fp32 (exact)
__device__ int            g_idx24[BATCH * N * K2];    // approx top-24
__device__ int            g_idx[BATCH * N * KNN];     // exact top-20
__device__ float          g_g[BATCH * N * NOUT];      // W1 . x_m
__device__ float          g_u[BATCH * N * NOUT];      // (W2-W1) . x_n

// ---------------- PTX helpers (baseline compute_103-legal) -----------------
__device__ __forceinline__ u32 smem_u32(const void* p) {
    u32 a;
    asm("{ .reg .u64 t; cvta.to.shared.u64 t, %1; cvt.u32.u64 %0, t; }"
        : "=r"(a) : "l"(p));
    return a;
}
__device__ __forceinline__ void ldsm_x4(u32& r0, u32& r1, u32& r2, u32& r3, u32 a) {
    asm volatile("ldmatrix.sync.aligned.m8n8.x4.shared.b16 {%0,%1,%2,%3}, [%4];"
                 : "=r"(r0), "=r"(r1), "=r"(r2), "=r"(r3) : "r"(a));
}
__device__ __forceinline__ void ldsm_x2(u32& r0, u32& r1, u32 a) {
    asm volatile("ldmatrix.sync.aligned.m8n8.x2.shared.b16 {%0,%1}, [%2];"
                 : "=r"(r0), "=r"(r1) : "r"(a));
}
__device__ __forceinline__ void mma16816(float* c, u32 a0, u32 a1, u32 a2, u32 a3,
                                         u32 b0, u32 b1) {
    asm volatile("mma.sync.aligned.m16n8k16.row.col.f32.bf16.bf16.f32 "
                 "{%0,%1,%2,%3}, {%4,%5,%6,%7}, {%8,%9}, {%0,%1,%2,%3};"
                 : "+f"(c[0]), "+f"(c[1]), "+f"(c[2]), "+f"(c[3])
                 : "r"(a0), "r"(a1), "r"(a2), "r"(a3), "r"(b0), "r"(b1));
}

// ---------------------------------------------------------------------------
// conv: x[b][c][n] fp32 -> xhi/xlo [b][n][c] bf16, xt [b][n][c] fp32, xx[b][n]
// ---------------------------------------------------------------------------
__global__ void conv_kernel(const float* __restrict__ x) {
    __shared__ float s[64][33];
    int b = blockIdx.y, n0 = blockIdx.x * 32, tid = threadIdx.x;
    const float* xb = x + (size_t)b * C * N;

#pragma unroll
    for (int it = 0; it < 8; it++) {
        int c = it * 8 + (tid >> 5), j = tid & 31;
        s[c][j] = xb[(size_t)c * N + n0 + j];
    }
    __syncthreads();

    if (tid < 32) {                       // exact xx (channel order 0..63)
        float acc = 0.f;
#pragma unroll
        for (int c = 0; c < 64; c++) { float v = s[c][tid]; acc = fmaf(v, v, acc); }
        g_xx[b * N + n0 + tid] = acc;
    }

    int nl = tid >> 3, seg = tid & 7;
    float v[8];
#pragma unroll
    for (int q = 0; q < 8; q++) v[q] = s[seg * 8 + q][nl];

    unsigned short hs[8], ls[8];
#pragma unroll
    for (int q = 0; q < 8; q++) {
        __nv_bfloat16 h = __float2bfloat16_rn(v[q]);
        __nv_bfloat16 l = __float2bfloat16_rn(v[q] - __bfloat162float(h));
        hs[q] = *(unsigned short*)&h;
        ls[q] = *(unsigned short*)&l;
    }
    size_t base = ((size_t)b * N + n0 + nl) * 64 + seg * 8;
    uint4 hv, lv;
    {
        unsigned short* p = (unsigned short*)&hv;
#pragma unroll
        for (int q = 0; q < 8; q++) p[q] = hs[q];
        p = (unsigned short*)&lv;
#pragma unroll
        for (int q = 0; q < 8; q++) p[q] = ls[q];
    }
    *(uint4*)&g_xhi[base] = hv;
    *(uint4*)&g_xlo[base] = lv;
    *(float4*)&g_xt[base]     = make_float4(v[0], v[1], v[2], v[3]);
    *(float4*)&g_xt[base + 4] = make_float4(v[4], v[5], v[6], v[7]);
}

// ---------------------------------------------------------------------------
// knn: HMMA bf16 3-term Gram + fused approx top-24.
// CTA = 128 n-rows, 256 thr (8 warps: warp_m=w&3 -> 32 rows, warp_n=w>>2 -> 64 cols)
// SMEM tiles padded to 144B rows (conflict-free ldmatrix).
// ---------------------------------------------------------------------------
#define RS 144                       // bytes per 64-bf16 row (128 + 16 pad)
#define SM_A_HI 0
#define SM_A_LO 18432
#define SM_B_HI 36864
#define SM_B_LO 55296
#define SM_XX   73728
#define SM_DIST 90112
#define DPAD 133
#define KNN_SMEM (SM_DIST + 128 * DPAD * 4)   // 158208 B

extern __shared__ char smem[];

__global__ __launch_bounds__(256, 1) void knn_kernel() {
    int tid = threadIdx.x, lane = tid & 31, w = tid >> 5;
    int warp_m = w & 3, warp_n = w >> 2;
    int b = blockIdx.y, n0 = blockIdx.x * 128;
    const u32 sb = smem_u32(smem);
    float* dist = (float*)(smem + SM_DIST);
    const float* xxs = (const float*)(smem + SM_XX);

    int lr = tid >> 1, ls = (tid & 1) * 4;   // loader: row, seg-quad

    // stationary A tiles (hi/lo) + whole-batch xx
    {
        size_t src = ((size_t)b * N + n0 + lr) * 64 + ls * 8;
#pragma unroll
        for (int q = 0; q < 4; q++) {
            *(uint4*)(smem + SM_A_HI + lr * RS + (ls + q) * 16) = *(const uint4*)&g_xhi[src + q * 8];
            *(uint4*)(smem + SM_A_LO + lr * RS + (ls + q) * 16) = *(const uint4*)&g_xlo[src + q * 8];
        }
        for (int i = tid; i < N / 4; i += 256)
            ((float4*)(smem + SM_XX))[i] = ((const float4*)&g_xx[(size_t)b * N])[i];
    }

    // ldmatrix lane addresses
    u32 a_addr_hi = sb + SM_A_HI + (warp_m * 32 + (lane & 15)) * RS + (lane >> 4) * 16;
    u32 a_addr_lo = a_addr_hi + (SM_A_LO - SM_A_HI);
    u32 b_row = warp_n * 64 + (lane & 7);
    u32 b_off = ((lane >> 3) & 1) * 16;
    u32 b_addr_hi = sb + SM_B_HI + b_row * RS + b_off;
    u32 b_addr_lo = b_addr_hi + (SM_B_LO - SM_B_HI);

    // top-K2 state: thread owns n = (tid&127), half (tid>=128 -> m offset 64)
    int own_n = tid & 127;
    int halfoff = (tid >= 128) ? 64 : 0;
    const float* drow = dist + own_n * DPAD + halfoff;

    float tv[K2];
    int   ti[K2];
#pragma unroll
    for (int k = 0; k < K2; k++) { tv[k] = NEG_INF; ti[k] = 0; }

    int scan_m0 = -1;

    for (int t = 0; t < 32; t++) {
        int m0 = t * 128;
        // issue next-B loads early (hidden behind scan)
        uint4 rbh[4], rbl[4];
        {
            size_t src = ((size_t)b * N + m0 + lr) * 64 + ls * 8;
#pragma unroll
            for (int q = 0; q < 4; q++) {
                rbh[q] = *(const uint4*)&g_xhi[src + q * 8];
                rbl[q] = *(const uint4*)&g_xlo[src + q * 8];
            }
        }
        // scan previous tile's scores
        if (scan_m0 >= 0) {
            for (int j = 0; j < 64; j++) {
                float s = drow[j];
                if (s > tv[K2 - 1]) {
                    float v = s; int vi = scan_m0 + j;
#pragma unroll
                    for (int k = 0; k < K2; k++) {
                        if (v > tv[k]) {
                            float t1 = tv[k]; tv[k] = v; v = t1;
                            int   t2 = ti[k]; ti[k] = vi; vi = t2;
                        }
                    }
                }
            }
        }
        // commit B tile to smem
#pragma unroll
        for (int q = 0; q < 4; q++) {
            *(uint4*)(smem + SM_B_HI + lr * RS + (ls + q) * 16) = rbh[q];
            *(uint4*)(smem + SM_B_LO + lr * RS + (ls + q) * 16) = rbl[q];
        }
        __syncthreads();

        // --- HMMA: acc[mi][nt][4], 3 terms ---
        float acc[2][8][4];
#pragma unroll
        for (int mi = 0; mi < 2; mi++)
#pragma unroll
            for (int nt = 0; nt < 8; nt++)
#pragma unroll
                for (int q = 0; q < 4; q++) acc[mi][nt][q] = 0.f;

#pragma unroll
        for (int ks = 0; ks < 4; ks++) {
            u32 ah[2][4], al[2][4];
#pragma unroll
            for (int mi = 0; mi < 2; mi++) {
                ldsm_x4(ah[mi][0], ah[mi][1], ah[mi][2], ah[mi][3],
                        a_addr_hi + mi * 16 * RS + ks * 32);
                ldsm_x4(al[mi][0], al[mi][1], al[mi][2], al[mi][3],
                        a_addr_lo + mi * 16 * RS + ks * 32);
            }
#pragma unroll
            for (int nt = 0; nt < 8; nt++) {
                u32 bh0, bh1, bl0, bl1;
                ldsm_x2(bh0, bh1, b_addr_hi + nt * 8 * RS + ks * 32);
                ldsm_x2(bl0, bl1, b_addr_lo + nt * 8 * RS + ks * 32);
#pragma unroll
                for (int mi = 0; mi < 2; mi++) {
                    mma16816(acc[mi][nt], ah[mi][0], ah[mi][1], ah[mi][2], ah[mi][3], bh0, bh1);
                    mma16816(acc[mi][nt], ah[mi][0], ah[mi][1], ah[mi][2], ah[mi][3], bl0, bl1);
                    mma16816(acc[mi][nt], al[mi][0], al[mi][1], al[mi][2], al[mi][3], bh0, bh1);
                }
            }
        }

        // --- scores -> dist[n][m] ---
        {
            int rb = warp_m * 32 + (lane >> 2);
            int cb = warp_n * 64 + 2 * (lane & 3);
#pragma unroll
            for (int mi = 0; mi < 2; mi++) {
#pragma unroll
                for (int nt = 0; nt < 8; nt++) {
                    int n_r = rb + mi * 16;
                    int m_c = cb + nt * 8;
                    float x0 = xxs[m0 + m_c], x1 = xxs[m0 + m_c + 1];
                    dist[n_r * DPAD + m_c]           = fmaf(2.f, acc[mi][nt][0], -x0);
                    dist[n_r * DPAD + m_c + 1]       = fmaf(2.f, acc[mi][nt][1], -x1);
                    dist[(n_r + 8) * DPAD + m_c]     = fmaf(2.f, acc[mi][nt][2], -x0);
                    dist[(n_r + 8) * DPAD + m_c + 1] = fmaf(2.f, acc[mi][nt][3], -x1);
                }
            }
        }
        __syncthreads();
        scan_m0 = m0 + halfoff;
    }
    // final tile scan
    {
        for (int j = 0; j < 64; j++) {
            float s = drow[j];
            if (s > tv[K2 - 1]) {
                float v = s; int vi = scan_m0 + j;
#pragma unroll
                for (int k = 0; k < K2; k++) {
                    if (v > tv[k]) {
                        float t1 = tv[k]; tv[k] = v; v = t1;
                        int   t2 = ti[k]; ti[k] = vi; vi = t2;
                    }
                }
            }
        }
    }
    __syncthreads();

    // merge halves: upper half dumps to smem, lower half merges + writes
    if (tid >= 128) {
        float* buf = dist + (tid - 128) * 48;
#pragma unroll
        for (int k = 0; k < K2; k++) { buf[k] = tv[k]; ((int*)buf)[K2 + k] = ti[k]; }
    }
    __syncthreads();
    if (tid < 128) {
        const float* buf = dist + tid * 48;
        for (int k = 0; k < K2; k++) {
            float v = buf[k];
            int vi = ((const int*)buf)[K2 + k];
            if (v > tv[K2 - 1] || (v == tv[K2 - 1] && vi < ti[K2 - 1])) {
#pragma unroll
                for (int q = 0; q < K2; q++) {
                    if (v > tv[q] || (v == tv[q] && vi < ti[q])) {
                        float t1 = tv[q]; tv[q] = v; v = t1;
                        int   t2 = ti[q]; ti[q] = vi; vi = t2;
                    }
                }
            }
        }
        int n = n0 + tid;
#pragma unroll
        for (int k = 0; k < K2; k++)
            g_idx24[((size_t)b * N + n) * K2 + k] = ti[k];
    }
}

// ---------------------------------------------------------------------------
// rescore: exact fp32 re-ranking of the 24 candidates -> exact top-20
// ---------------------------------------------------------------------------
__global__ void rescore_kernel() {
    int b = blockIdx.y, w = threadIdx.x >> 5, lane = threadIdx.x & 31;
    int n = blockIdx.x * 8 + w;

    const float2 un = *(const float2*)&g_xt[((size_t)b * N + n) * 64 + lane * 2];
    const int* ip = &g_idx24[((size_t)b * N + n) * K2];

    float tv[KNN];
    int   ti[KNN];
#pragma unroll
    for (int k = 0; k < KNN; k++) { tv[k] = NEG_INF; ti[k] = 0x7fffffff; }

    for (int k = 0; k < K2; k++) {
        int m = ip[k];
        const float2 vm = *(const float2*)&g_xt[((size_t)b * N + m) * 64 + lane * 2];
        float p = un.x * vm.x + un.y * vm.y;
#pragma unroll
        for (int off = 16; off > 0; off >>= 1)
            p += __shfl_xor_sync(0xffffffffu, p, off);
        float s = 2.f * p - g_xx[b * N + m];
        bool better = (s > tv[KNN - 1]) || (s == tv[KNN - 1] && m < ti[KNN - 1]);
        if (better) {
            float v = s; int vi = m;
#pragma unroll
            for (int q = 0; q < KNN; q++) {
                if (v > tv[q] || (v == tv[q] && vi < ti[q])) {
                    float t1 = tv[q]; tv[q] = v; v = t1;
                    int   t2 = ti[q]; ti[q] = vi; vi = t2;
                }
            }
        }
    }
    if (lane == 0) {
#pragma unroll
        for (int k = 0; k < KNN; k++)
            g_idx[((size_t)b * N + n) * KNN + k] = ti[k];
    }
}

// ---------------------------------------------------------------------------
// proj: g = W1.x, u = (W2-W1).x
// ---------------------------------------------------------------------------
__global__ void proj_kernel(const float* __restrict__ x, const float* __restrict__ W) {
    __shared__ float Ws[64 * 128];
    int b = blockIdx.y;
    int m = blockIdx.x * 128 + threadIdx.x;
    for (int i = threadIdx.x; i < 64 * 128; i += 128) Ws[i] = W[i];
    __syncthreads();

    const float* xb = x + (size_t)b * C * N;
    float xr[64];
#pragma unroll
    for (int c = 0; c < 64; c++) xr[c] = xb[c * N + m];

    float* gp = g_g + ((size_t)b * N + m) * NOUT;
    float* up = g_u + ((size_t)b * N + m) * NOUT;

    for (int o = 0; o < 64; o += 4) {
        float ag[4] = {0.f, 0.f, 0.f, 0.f};
        float at[4] = {0.f, 0.f, 0.f, 0.f};
#pragma unroll
        for (int q = 0; q < 4; q++) {
#pragma unroll
            for (int c4 = 0; c4 < 16; c4++) {
                float4 w1 = *(const float4*)&Ws[(o + q) * 128 + c4 * 4];
                float4 w2 = *(const float4*)&Ws[(o + q) * 128 + 64 + c4 * 4];
                ag[q] = fmaf(w1.x, xr[c4 * 4 + 0], ag[q]);
                ag[q] = fmaf(w1.y, xr[c4 * 4 + 1], ag[q]);
                ag[q] = fmaf(w1.z, xr[c4 * 4 + 2], ag[q]);
                ag[q] = fmaf(w1.w, xr[c4 * 4 + 3], ag[q]);
                at[q] = fmaf(w2.x, xr[c4 * 4 + 0], at[q]);
                at[q] = fmaf(w2.y, xr[c4 * 4 + 1], at[q]);
                at[q] = fmaf(w2.z, xr[c4 * 4 + 2], at[q]);
                at[q] = fmaf(w2.w, xr[c4 * 4 + 3], at[q]);
            }
        }
        *(float4*)&gp[o] = make_float4(ag[0], ag[1], ag[2], ag[3]);
        *(float4*)&up[o] = make_float4(at[0] - ag[0], at[1] - ag[1],
                                       at[2] - ag[2], at[3] - ag[3]);
    }
}

// ---------------------------------------------------------------------------
// out: gather + max + leaky-relu
// ---------------------------------------------------------------------------
__global__ void out_kernel(float* __restrict__ out) {
    __shared__ float os[64 * 33];
    int b = blockIdx.y;
    int w = threadIdx.x >> 5, lane = threadIdx.x & 31;
    int n = blockIdx.x * 32 + w;

    const float* up = g_u + ((size_t)b * N + n) * NOUT;
    float u0 = up[lane], u1 = up[lane + 32];
    const int* ip = g_idx + ((size_t)b * N + n) * KNN;

    float best0 = NEG_INF, best1 = NEG_INF;
#pragma unroll
    for (int k = 0; k < KNN; k++) {
        int m = ip[k];
        const float* gp = g_g + ((size_t)b * N + m) * NOUT;
        best0 = fmaxf(best0, gp[lane] + u0);
        best1 = fmaxf(best1, gp[lane + 32] + u1);
    }
    best0 = best0 >= 0.f ? best0 : SLOPE * best0;
    best1 = best1 >= 0.f ? best1 : SLOPE * best1;

    os[lane * 33 + w] = best0;
    os[(lane + 32) * 33 + w] = best1;
    __syncthreads();

    for (int i = threadIdx.x; i < 64 * 32; i += 1024) {
        int o = i >> 5, j = i & 31;
        out[((size_t)b * 64 + o) * N + blockIdx.x * 32 + j] = os[o * 33 + j];
    }
}

// ---------------------------------------------------------------------------
extern "C" void kernel_launch(void* const* d_in, const int* in_sizes, int n_in,
                              void* d_out, int out_size) {
    const float* x = (const float*)d_in[0];   // (8, 64, 4096)
    const float* W = (const float*)d_in[1];   // (64, 128)
    float* out = (float*)d_out;               // (8, 64, 4096)

    cudaFuncSetAttribute(knn_kernel, cudaFuncAttributeMaxDynamicSharedMemorySize,
                         KNN_SMEM);

    conv_kernel<<<dim3(N / 32, BATCH), 256>>>(x);
    knn_kernel<<<dim3(N / 128, BATCH), 256, KNN_SMEM>>>();
    rescore_kernel<<<dim3(N / 8, BATCH), 256>>>();
    proj_kernel<<<dim3(N / 128, BATCH), 128>>>(x, W);
    out_kernel<<<dim3(N / 32, BATCH), 1024>>>(out);
}